// round 2
// baseline (speedup 1.0000x reference)
#include <cuda_runtime.h>
#include <cuda_bf16.h>
#include <math.h>

// Problem constants
constexpr int B_   = 2;
constexpr int S_   = 2048;
constexpr int HID_ = 1024;
constexpr int NH_  = 16;
constexpr int DK_  = 64;
constexpr int M_   = B_ * S_;   // 4096 rows for projection GEMMs

// ---------------------------------------------------------------------------
// Scratch (device globals; no allocation allowed)
// ---------------------------------------------------------------------------
__device__ float g_kin[B_ * S_ * HID_];   // key  * (1+bias)
__device__ float g_vin[B_ * S_ * HID_];   // value* (1+bias)
__device__ float g_q  [B_ * NH_ * S_ * DK_];
__device__ float g_k  [B_ * NH_ * S_ * DK_];
__device__ float g_v  [B_ * NH_ * S_ * DK_];
__device__ float g_att[B_ * S_ * HID_];   // attention output, [B,S,HID]

// ---------------------------------------------------------------------------
// 1) scale K/V by (1 + bias)
// ---------------------------------------------------------------------------
__global__ void scale_kv_kernel(const float* __restrict__ key,
                                const float* __restrict__ value,
                                const float* __restrict__ bias) {
    int i = blockIdx.x * blockDim.x + threadIdx.x;
    const int n = B_ * S_ * HID_;
    if (i < n) {
        int row = i / HID_;              // b*S + s
        float f = 1.0f + bias[row];
        g_kin[i] = key[i]   * f;
        g_vin[i] = value[i] * f;
    }
}

// ---------------------------------------------------------------------------
// 2) SGEMM: C = A @ W^T + bias.   A: [M,1024] row-major, W: [1024,1024] row-major
//    MODE 0: C row-major [M,1024]
//    MODE 1: write into [B,NH,S,DK] layout (for Q/K/V projections)
//    128x128x8 tiling, 256 threads, 8x8 per thread.
// ---------------------------------------------------------------------------
template <int MODE>
__global__ __launch_bounds__(256)
void sgemm_kernel(const float* __restrict__ A,
                  const float* __restrict__ W,
                  const float* __restrict__ bias,
                  float* __restrict__ C) {
    constexpr int K = 1024;
    constexpr int N = 1024;

    __shared__ float As[8][128];
    __shared__ float Bs[8][128];

    const int tid = threadIdx.x;
    const int tx  = tid % 16;      // n-dim
    const int ty  = tid / 16;      // m-dim
    const int m0  = blockIdx.y * 128;
    const int n0  = blockIdx.x * 128;

    const int lrow = tid >> 1;           // 0..127
    const int lcol = (tid & 1) * 4;      // 0 or 4

    float acc[8][8];
#pragma unroll
    for (int i = 0; i < 8; i++)
#pragma unroll
        for (int j = 0; j < 8; j++) acc[i][j] = 0.0f;

    const float* Aptr = A + (m0 + lrow) * K + lcol;
    const float* Wptr = W + (n0 + lrow) * K + lcol;

    for (int k0 = 0; k0 < K; k0 += 8) {
        float4 a  = *(const float4*)(Aptr + k0);
        float4 bw = *(const float4*)(Wptr + k0);
        __syncthreads();
        As[lcol + 0][lrow] = a.x;  As[lcol + 1][lrow] = a.y;
        As[lcol + 2][lrow] = a.z;  As[lcol + 3][lrow] = a.w;
        Bs[lcol + 0][lrow] = bw.x; Bs[lcol + 1][lrow] = bw.y;
        Bs[lcol + 2][lrow] = bw.z; Bs[lcol + 3][lrow] = bw.w;
        __syncthreads();

#pragma unroll
        for (int kk = 0; kk < 8; kk++) {
            float af[8], bf[8];
#pragma unroll
            for (int i = 0; i < 8; i++) af[i] = As[kk][ty * 8 + i];
#pragma unroll
            for (int j = 0; j < 8; j++) bf[j] = Bs[kk][tx * 8 + j];
#pragma unroll
            for (int i = 0; i < 8; i++)
#pragma unroll
                for (int j = 0; j < 8; j++) acc[i][j] += af[i] * bf[j];
        }
    }

#pragma unroll
    for (int i = 0; i < 8; i++) {
        int m = m0 + ty * 8 + i;
#pragma unroll
        for (int j = 0; j < 8; j++) {
            int n = n0 + tx * 8 + j;
            float val = acc[i][j] + bias[n];
            if (MODE == 0) {
                C[m * N + n] = val;
            } else {
                int b = m >> 11;          // m / S_
                int s = m & (S_ - 1);
                int h = n >> 6;           // n / DK_
                int d = n & (DK_ - 1);
                C[((b * NH_ + h) * S_ + s) * DK_ + d] = val;
            }
        }
    }
}

// ---------------------------------------------------------------------------
// 3) Attention: per-(b,h), 16 query rows per block, full-row softmax in SMEM.
//    grid (S/16, NH, B), 256 threads.
//    dynamic smem: scores[16][2048] = 128 KB
// ---------------------------------------------------------------------------
constexpr int BQ_ = 16;

__global__ __launch_bounds__(256)
void attn_kernel(const int* __restrict__ mask, float* __restrict__ out) {
    extern __shared__ float scores[];          // [BQ_][S_]
    __shared__ float Qs[BQ_][DK_ + 1];
    __shared__ float Ks[64][DK_ + 1];
    __shared__ float rowinv[BQ_];

    const int tid = threadIdx.x;
    const int b   = blockIdx.z;
    const int h   = blockIdx.y;
    const int q0  = blockIdx.x * BQ_;

    const float* Qb = g_q + ((size_t)(b * NH_ + h) * S_) * DK_;
    const float* Kb = g_k + ((size_t)(b * NH_ + h) * S_) * DK_;
    const float* Vb = g_v + ((size_t)(b * NH_ + h) * S_) * DK_;
    const int*   mb = mask + b * S_;

    // load Q tile
    for (int i = tid; i < BQ_ * DK_; i += 256) {
        int q = i / DK_, d = i % DK_;
        Qs[q][d] = Qb[(q0 + q) * DK_ + d];
    }
    __syncthreads();

    const float scale = 0.125f;   // 1/sqrt(64)
    const int kl = tid % 64;      // local k within tile
    const int qg = tid / 64;      // 0..3

    // ---- scores = QK^T * scale, masked ----
    for (int kt = 0; kt < S_; kt += 64) {
        for (int i = tid; i < 64 * DK_; i += 256) {
            int k = i / DK_, d = i % DK_;
            Ks[k][d] = Kb[(kt + k) * DK_ + d];
        }
        __syncthreads();

        const int kglob = kt + kl;
        const bool masked = (mb[kglob] == 0);
#pragma unroll
        for (int j = 0; j < 4; j++) {
            int qi = qg + 4 * j;
            float acc = 0.0f;
#pragma unroll
            for (int d = 0; d < DK_; d++) acc += Qs[qi][d] * Ks[kl][d];
            scores[qi * S_ + kglob] = masked ? -10000.0f : acc * scale;
        }
        __syncthreads();
    }

    // ---- softmax over full rows (16 threads per row) ----
    {
        const int row    = tid / 16;
        const int lane16 = tid % 16;
        float* srow = scores + row * S_;

        float mx = -3.4e38f;
        for (int k = lane16; k < S_; k += 16) mx = fmaxf(mx, srow[k]);
#pragma unroll
        for (int o = 8; o > 0; o >>= 1)
            mx = fmaxf(mx, __shfl_xor_sync(0xFFFFFFFFu, mx, o));

        float sum = 0.0f;
        for (int k = lane16; k < S_; k += 16) {
            float e = __expf(srow[k] - mx);
            srow[k] = e;
            sum += e;
        }
#pragma unroll
        for (int o = 8; o > 0; o >>= 1)
            sum += __shfl_xor_sync(0xFFFFFFFFu, sum, o);

        if (lane16 == 0) rowinv[row] = 1.0f / sum;
    }
    __syncthreads();

    // ---- out = P @ V  (thread owns (4 q-rows, one d) column) ----
    {
        const int d = tid % 64;
        float acc0 = 0.f, acc1 = 0.f, acc2 = 0.f, acc3 = 0.f;
        const float* p0 = scores + (qg +  0) * S_;
        const float* p1 = scores + (qg +  4) * S_;
        const float* p2 = scores + (qg +  8) * S_;
        const float* p3 = scores + (qg + 12) * S_;
        const float* vp = Vb + d;
#pragma unroll 4
        for (int k = 0; k < S_; k++) {
            float v = vp[k * DK_];
            acc0 += p0[k] * v;
            acc1 += p1[k] * v;
            acc2 += p2[k] * v;
            acc3 += p3[k] * v;
        }
        const int col = h * DK_ + d;
        out[((size_t)b * S_ + q0 + qg +  0) * HID_ + col] = acc0 * rowinv[qg +  0];
        out[((size_t)b * S_ + q0 + qg +  4) * HID_ + col] = acc1 * rowinv[qg +  4];
        out[((size_t)b * S_ + q0 + qg +  8) * HID_ + col] = acc2 * rowinv[qg +  8];
        out[((size_t)b * S_ + q0 + qg + 12) * HID_ + col] = acc3 * rowinv[qg + 12];
    }
}

// ---------------------------------------------------------------------------
// launch
// ---------------------------------------------------------------------------
extern "C" void kernel_launch(void* const* d_in, const int* in_sizes, int n_in,
                              void* d_out, int out_size) {
    const float* query = (const float*)d_in[0];
    const float* key   = (const float*)d_in[1];
    const float* value = (const float*)d_in[2];
    const float* bias  = (const float*)d_in[3];
    const int*   mask  = (const int*)  d_in[4];
    const float* wq    = (const float*)d_in[5];
    const float* bq    = (const float*)d_in[6];
    const float* wk    = (const float*)d_in[7];
    const float* bk    = (const float*)d_in[8];
    const float* wv    = (const float*)d_in[9];
    const float* bv    = (const float*)d_in[10];
    const float* wo    = (const float*)d_in[11];
    const float* bo    = (const float*)d_in[12];
    float* out = (float*)d_out;

    // resolve scratch symbol addresses
    float *p_kin, *p_vin, *p_q, *p_k, *p_v, *p_att;
    cudaGetSymbolAddress((void**)&p_kin, g_kin);
    cudaGetSymbolAddress((void**)&p_vin, g_vin);
    cudaGetSymbolAddress((void**)&p_q,   g_q);
    cudaGetSymbolAddress((void**)&p_k,   g_k);
    cudaGetSymbolAddress((void**)&p_v,   g_v);
    cudaGetSymbolAddress((void**)&p_att, g_att);

    // 1) scale K/V
    {
        const int n = B_ * S_ * HID_;
        scale_kv_kernel<<<(n + 255) / 256, 256>>>(key, value, bias);
    }

    // 2) projections (write [B,NH,S,DK])
    {
        dim3 grid(1024 / 128, M_ / 128);   // (8, 32)
        sgemm_kernel<1><<<grid, 256>>>(query, wq, bq, p_q);
        sgemm_kernel<1><<<grid, 256>>>(p_kin, wk, bk, p_k);
        sgemm_kernel<1><<<grid, 256>>>(p_vin, wv, bv, p_v);
    }

    // 3) attention
    {
        static_assert(BQ_ * S_ * sizeof(float) == 131072, "smem size");
        cudaFuncSetAttribute(attn_kernel,
                             cudaFuncAttributeMaxDynamicSharedMemorySize,
                             BQ_ * S_ * sizeof(float));
        dim3 grid(S_ / BQ_, NH_, B_);      // (128, 16, 2)
        attn_kernel<<<grid, 256, BQ_ * S_ * sizeof(float)>>>(mask, p_att);
    }

    // 4) output projection (row-major out)
    {
        dim3 grid(1024 / 128, M_ / 128);
        sgemm_kernel<0><<<grid, 256>>>(p_att, wo, bo, out);
    }
}

// round 4
// speedup vs baseline: 2.6584x; 2.6584x over previous
#include <cuda_runtime.h>
#include <cuda_bf16.h>
#include <math.h>

// Problem constants
constexpr int B_   = 2;
constexpr int S_   = 2048;
constexpr int HID_ = 1024;
constexpr int NH_  = 16;
constexpr int DK_  = 64;
constexpr int M_   = B_ * S_;   // 4096 rows for projection GEMMs

// ---------------------------------------------------------------------------
// Scratch (device globals; no allocation allowed)
// ---------------------------------------------------------------------------
__device__ float g_kin[B_ * S_ * HID_];   // key  * (1+bias)
__device__ float g_vin[B_ * S_ * HID_];   // value* (1+bias)
__device__ float g_q  [B_ * NH_ * S_ * DK_];
__device__ float g_k  [B_ * NH_ * S_ * DK_];
__device__ float g_v  [B_ * NH_ * S_ * DK_];
__device__ float g_att[B_ * S_ * HID_];   // attention output, [B,S,HID]
__device__ float g_p  [B_ * NH_ * S_ * S_]; // raw masked scores, 1 GiB

// ---------------------------------------------------------------------------
// 1) scale K/V by (1 + bias)
// ---------------------------------------------------------------------------
__global__ void scale_kv_kernel(const float* __restrict__ key,
                                const float* __restrict__ value,
                                const float* __restrict__ bias) {
    int i = blockIdx.x * blockDim.x + threadIdx.x;
    const int n = B_ * S_ * HID_;
    if (i < n) {
        int row = i / HID_;              // b*S + s
        float f = 1.0f + bias[row];
        g_kin[i] = key[i]   * f;
        g_vin[i] = value[i] * f;
    }
}

// ---------------------------------------------------------------------------
// 2) SGEMM: C = A @ W^T + bias.   A: [M,1024], W: [1024,1024] row-major
//    MODE 0: C row-major [M,1024];  MODE 1: C in [B,NH,S,DK] layout
// ---------------------------------------------------------------------------
template <int MODE>
__global__ __launch_bounds__(256)
void sgemm_kernel(const float* __restrict__ A,
                  const float* __restrict__ W,
                  const float* __restrict__ bias,
                  float* __restrict__ C) {
    constexpr int K = 1024;
    constexpr int N = 1024;

    __shared__ float As[8][128];
    __shared__ float Bs[8][128];

    const int tid = threadIdx.x;
    const int tx  = tid % 16;      // n-dim
    const int ty  = tid / 16;      // m-dim
    const int m0  = blockIdx.y * 128;
    const int n0  = blockIdx.x * 128;

    const int lrow = tid >> 1;           // 0..127
    const int lcol = (tid & 1) * 4;      // 0 or 4

    float acc[8][8];
#pragma unroll
    for (int i = 0; i < 8; i++)
#pragma unroll
        for (int j = 0; j < 8; j++) acc[i][j] = 0.0f;

    const float* Aptr = A + (m0 + lrow) * K + lcol;
    const float* Wptr = W + (n0 + lrow) * K + lcol;

    for (int k0 = 0; k0 < K; k0 += 8) {
        float4 a  = *(const float4*)(Aptr + k0);
        float4 bw = *(const float4*)(Wptr + k0);
        __syncthreads();
        As[lcol + 0][lrow] = a.x;  As[lcol + 1][lrow] = a.y;
        As[lcol + 2][lrow] = a.z;  As[lcol + 3][lrow] = a.w;
        Bs[lcol + 0][lrow] = bw.x; Bs[lcol + 1][lrow] = bw.y;
        Bs[lcol + 2][lrow] = bw.z; Bs[lcol + 3][lrow] = bw.w;
        __syncthreads();

#pragma unroll
        for (int kk = 0; kk < 8; kk++) {
            float af[8], bf[8];
#pragma unroll
            for (int i = 0; i < 8; i++) af[i] = As[kk][ty * 8 + i];
#pragma unroll
            for (int j = 0; j < 8; j++) bf[j] = Bs[kk][tx * 8 + j];
#pragma unroll
            for (int i = 0; i < 8; i++)
#pragma unroll
                for (int j = 0; j < 8; j++) acc[i][j] += af[i] * bf[j];
        }
    }

#pragma unroll
    for (int i = 0; i < 8; i++) {
        int m = m0 + ty * 8 + i;
#pragma unroll
        for (int j = 0; j < 8; j++) {
            int n = n0 + tx * 8 + j;
            float val = acc[i][j] + bias[n];
            if (MODE == 0) {
                C[m * N + n] = val;
            } else {
                int b = m >> 11;          // m / S_
                int s = m & (S_ - 1);
                int h = n >> 6;           // n / DK_
                int d = n & (DK_ - 1);
                C[((b * NH_ + h) * S_ + s) * DK_ + d] = val;
            }
        }
    }
}

// ---------------------------------------------------------------------------
// 3a) QK^T: per (b,h), 128x128 score tile, GEMM-style. Writes raw masked
//     scaled scores to g_p.  grid (S/128, S/128, B*NH), 256 thr, 66KB dyn smem
// ---------------------------------------------------------------------------
__global__ __launch_bounds__(256)
void qk_kernel(const float* __restrict__ Q, const float* __restrict__ K,
               const int* __restrict__ mask, float* __restrict__ P) {
    extern __shared__ float sm[];
    float* Qs = sm;                    // [64][128]  (d-major, transposed)
    float* Ks = sm + DK_ * 128;        // [64][128]
    int*   msk = (int*)(sm + 2 * DK_ * 128);

    const int tid = threadIdx.x;
    const int bh  = blockIdx.z;
    const int b   = bh >> 4;
    const int q0  = blockIdx.y * 128;
    const int k0  = blockIdx.x * 128;

    const float* Qb = Q + (size_t)bh * S_ * DK_;
    const float* Kb = K + (size_t)bh * S_ * DK_;
    float*       Pb = P + (size_t)bh * S_ * S_;

    // load tiles transposed into [d][m] layout
#pragma unroll
    for (int i = 0; i < 8; i++) {
        int f = tid + i * 256;
        int r = f >> 4;            // 0..127
        int c = (f & 15) * 4;      // 0..60
        float4 qv = *(const float4*)(Qb + (size_t)(q0 + r) * DK_ + c);
        Qs[(c + 0) * 128 + r] = qv.x; Qs[(c + 1) * 128 + r] = qv.y;
        Qs[(c + 2) * 128 + r] = qv.z; Qs[(c + 3) * 128 + r] = qv.w;
        float4 kv = *(const float4*)(Kb + (size_t)(k0 + r) * DK_ + c);
        Ks[(c + 0) * 128 + r] = kv.x; Ks[(c + 1) * 128 + r] = kv.y;
        Ks[(c + 2) * 128 + r] = kv.z; Ks[(c + 3) * 128 + r] = kv.w;
    }
    if (tid < 128) msk[tid] = mask[b * S_ + k0 + tid];
    __syncthreads();

    const int tx = tid & 15;
    const int ty = tid >> 4;

    float acc[8][8];
#pragma unroll
    for (int i = 0; i < 8; i++)
#pragma unroll
        for (int j = 0; j < 8; j++) acc[i][j] = 0.0f;

#pragma unroll 4
    for (int d = 0; d < DK_; d++) {
        float4 a0 = *(const float4*)&Qs[d * 128 + ty * 8];
        float4 a1 = *(const float4*)&Qs[d * 128 + ty * 8 + 4];
        float4 b0 = *(const float4*)&Ks[d * 128 + tx * 8];
        float4 b1 = *(const float4*)&Ks[d * 128 + tx * 8 + 4];
        float af[8] = {a0.x, a0.y, a0.z, a0.w, a1.x, a1.y, a1.z, a1.w};
        float bf[8] = {b0.x, b0.y, b0.z, b0.w, b1.x, b1.y, b1.z, b1.w};
#pragma unroll
        for (int i = 0; i < 8; i++)
#pragma unroll
            for (int j = 0; j < 8; j++) acc[i][j] += af[i] * bf[j];
    }

    // store raw masked scores (coalesced: tx*8 contiguous across warp)
    int mj[8];
#pragma unroll
    for (int j = 0; j < 8; j++) mj[j] = msk[tx * 8 + j];
#pragma unroll
    for (int i = 0; i < 8; i++) {
        float* prow = Pb + (size_t)(q0 + ty * 8 + i) * S_ + k0 + tx * 8;
#pragma unroll
        for (int j = 0; j < 8; j++)
            prow[j] = mj[j] ? acc[i][j] * 0.125f : -10000.0f;
    }
}

// ---------------------------------------------------------------------------
// 3b) fused softmax + P@V: block = 128 q rows x 64 d (full head dim).
//     pass1: per-row max & sum of exp (row re-read hits L1: 8KB/row).
//     pass2: GEMM over k, exp applied at smem staging, 1/sum in epilogue.
//     grid (S/128, B*NH), 256 threads.
// ---------------------------------------------------------------------------
__global__ __launch_bounds__(256)
void pv_kernel(const float* __restrict__ P, const float* __restrict__ V,
               float* __restrict__ out) {
    __shared__ float As[16][129];     // [k][q] transposed, padded
    __shared__ float Bs[16][64];      // [k][d]
    __shared__ float mxs[128];
    __shared__ float rinv[128];

    const int tid = threadIdx.x;
    const int bh  = blockIdx.y;
    const int b   = bh >> 4;
    const int h   = bh & 15;
    const int q0  = blockIdx.x * 128;

    const float* Pb = P + (size_t)bh * S_ * S_;
    const float* Vb = V + (size_t)bh * S_ * DK_;

    // ---- pass 1: row max + sumexp (warp per row, 16 rows per warp) ----
    {
        const int lane = tid & 31;
        const int w    = tid >> 5;
        for (int rr = 0; rr < 16; rr++) {
            const int row = w * 16 + rr;
            const float* pr = Pb + (size_t)(q0 + row) * S_;
            float mx = -3.4e38f;
            for (int j = lane; j < S_ / 4; j += 32) {
                float4 x = *(const float4*)(pr + j * 4);
                mx = fmaxf(mx, fmaxf(fmaxf(x.x, x.y), fmaxf(x.z, x.w)));
            }
#pragma unroll
            for (int o = 16; o > 0; o >>= 1)
                mx = fmaxf(mx, __shfl_xor_sync(0xFFFFFFFFu, mx, o));
            float sum = 0.0f;
            for (int j = lane; j < S_ / 4; j += 32) {
                float4 x = *(const float4*)(pr + j * 4);
                sum += __expf(x.x - mx) + __expf(x.y - mx)
                     + __expf(x.z - mx) + __expf(x.w - mx);
            }
#pragma unroll
            for (int o = 16; o > 0; o >>= 1)
                sum += __shfl_xor_sync(0xFFFFFFFFu, sum, o);
            if (lane == 0) { mxs[row] = mx; rinv[row] = 1.0f / sum; }
        }
    }
    __syncthreads();

    // ---- pass 2: GEMM out[q][d] = sum_k exp(P[q][k]-mx[q]) * V[k][d] ----
    const int tx = tid & 15;   // d
    const int ty = tid >> 4;   // q
    float acc[8][4];
#pragma unroll
    for (int i = 0; i < 8; i++)
#pragma unroll
        for (int j = 0; j < 4; j++) acc[i][j] = 0.0f;

    for (int kt = 0; kt < S_; kt += 16) {
        __syncthreads();
        // stage P chunk (128 q x 16 k), exp applied, transposed into As[k][q]
#pragma unroll
        for (int i = 0; i < 2; i++) {
            int f = tid + i * 256;
            int r  = f >> 2;          // q row 0..127
            int c4 = (f & 3) * 4;     // k col 0,4,8,12
            float4 x = *(const float4*)(Pb + (size_t)(q0 + r) * S_ + kt + c4);
            float m = mxs[r];
            As[c4 + 0][r] = __expf(x.x - m);
            As[c4 + 1][r] = __expf(x.y - m);
            As[c4 + 2][r] = __expf(x.z - m);
            As[c4 + 3][r] = __expf(x.w - m);
        }
        // stage V chunk (16 k x 64 d)
        {
            int r = tid >> 4, c = (tid & 15) * 4;
            *(float4*)&Bs[r][c] = *(const float4*)(Vb + (size_t)(kt + r) * DK_ + c);
        }
        __syncthreads();

#pragma unroll
        for (int kk = 0; kk < 16; kk++) {
            float4 bv = *(const float4*)&Bs[kk][tx * 4];
            float af[8];
#pragma unroll
            for (int i = 0; i < 8; i++) af[i] = As[kk][ty * 8 + i];
            float bf[4] = {bv.x, bv.y, bv.z, bv.w};
#pragma unroll
            for (int i = 0; i < 8; i++)
#pragma unroll
                for (int j = 0; j < 4; j++) acc[i][j] += af[i] * bf[j];
        }
    }

    // epilogue: normalize and store to [B,S,HID]
#pragma unroll
    for (int i = 0; i < 8; i++) {
        const int lr = ty * 8 + i;
        const float rv = rinv[lr];
        float4 o;
        o.x = acc[i][0] * rv; o.y = acc[i][1] * rv;
        o.z = acc[i][2] * rv; o.w = acc[i][3] * rv;
        *(float4*)(out + ((size_t)b * S_ + q0 + lr) * HID_ + h * DK_ + tx * 4) = o;
    }
}

// ---------------------------------------------------------------------------
// launch
// ---------------------------------------------------------------------------
extern "C" void kernel_launch(void* const* d_in, const int* in_sizes, int n_in,
                              void* d_out, int out_size) {
    const float* query = (const float*)d_in[0];
    const float* key   = (const float*)d_in[1];
    const float* value = (const float*)d_in[2];
    const float* bias  = (const float*)d_in[3];
    const int*   mask  = (const int*)  d_in[4];
    const float* wq    = (const float*)d_in[5];
    const float* bq    = (const float*)d_in[6];
    const float* wk    = (const float*)d_in[7];
    const float* bk    = (const float*)d_in[8];
    const float* wv    = (const float*)d_in[9];
    const float* bv    = (const float*)d_in[10];
    const float* wo    = (const float*)d_in[11];
    const float* bo    = (const float*)d_in[12];
    float* out = (float*)d_out;

    float *p_kin, *p_vin, *p_q, *p_k, *p_v, *p_att, *p_p;
    cudaGetSymbolAddress((void**)&p_kin, g_kin);
    cudaGetSymbolAddress((void**)&p_vin, g_vin);
    cudaGetSymbolAddress((void**)&p_q,   g_q);
    cudaGetSymbolAddress((void**)&p_k,   g_k);
    cudaGetSymbolAddress((void**)&p_v,   g_v);
    cudaGetSymbolAddress((void**)&p_att, g_att);
    cudaGetSymbolAddress((void**)&p_p,   g_p);

    // 1) scale K/V
    {
        const int n = B_ * S_ * HID_;
        scale_kv_kernel<<<(n + 255) / 256, 256>>>(key, value, bias);
    }

    // 2) projections (write [B,NH,S,DK])
    {
        dim3 grid(1024 / 128, M_ / 128);   // (8, 32)
        sgemm_kernel<1><<<grid, 256>>>(query, wq, bq, p_q);
        sgemm_kernel<1><<<grid, 256>>>(p_kin, wk, bk, p_k);
        sgemm_kernel<1><<<grid, 256>>>(p_vin, wv, bv, p_v);
    }

    // 3a) QK^T -> raw masked scores
    {
        const int smem = (2 * DK_ * 128) * sizeof(float) + 128 * sizeof(int);
        cudaFuncSetAttribute(qk_kernel,
                             cudaFuncAttributeMaxDynamicSharedMemorySize, smem);
        dim3 grid(S_ / 128, S_ / 128, B_ * NH_);   // (16,16,32)
        qk_kernel<<<grid, 256, smem>>>(p_q, p_k, mask, p_p);
    }

    // 3b) fused softmax + P@V
    {
        dim3 grid(S_ / 128, B_ * NH_);             // (16,32)
        pv_kernel<<<grid, 256>>>(p_p, p_v, p_att);
    }

    // 4) output projection
    {
        dim3 grid(1024 / 128, M_ / 128);
        sgemm_kernel<0><<<grid, 256>>>(p_att, wo, bo, out);
    }
}